// round 12
// baseline (speedup 1.0000x reference)
#include <cuda_runtime.h>
#include <math.h>
#include <stdint.h>

// Problem constants
#define BATCH 8
#define CHN   64
#define PIX   1024
#define PQ    256
#define GRP   32
#define HW    16384   // 128*128
#define KTOP  21      // int(32/3*2)

// ---------------- scratch (static device globals; no allocation) ----------------
__device__ uint32_t d_pooled_t[BATCH*CHN*PIX];   // tf32
__device__ uint32_t d_xpre3  [256*3072];         // [hi | lo | hi] per row
__device__ uint32_t d_WT_t   [PIX*PIX];          // gcn_weight^T tf32
__device__ uint32_t d_vw_t   [PIX*PIX];          // gcn_v_w tf32
__device__ uint32_t d_kw_t   [PQ*PIX];           // k_w tf32
__device__ uint32_t d_valw_t [PIX*PIX];          // v_w tf32
__device__ uint32_t d_qw_t   [PQ*PIX];           // q_w tf32
__device__ uint32_t d_qw3    [PQ*3072];          // gcn_q_w [hi | hi | lo]
__device__ uint32_t d_kw3    [PQ*3072];          // gcn_k_w [hi | hi | lo]
__device__ uint32_t d_av_t   [BATCH*GRP*PIX];    // tf32
__device__ float    d_gcnout [BATCH*GRP*PIX];
__device__ uint32_t d_gcnout_t[BATCH*GRP*PIX];   // tf32
__device__ float d_key   [BATCH*CHN*PQ];         // reduced key (phase-2 reduce)
__device__ float d_tuT   [BATCH*PIX*CHN];
__device__ float d_Gpart [BATCH*8*CHN*CHN];
__device__ float d_part  [8388608];              // split-K partials (32 MB)

// ---------------- helpers ----------------
__device__ __forceinline__ float wmax(float v) {
    #pragma unroll
    for (int o = 16; o > 0; o >>= 1) v = fmaxf(v, __shfl_xor_sync(0xffffffffu, v, o));
    return v;
}
__device__ __forceinline__ float wsum(float v) {
    #pragma unroll
    for (int o = 16; o > 0; o >>= 1) v += __shfl_xor_sync(0xffffffffu, v, o);
    return v;
}
__device__ __forceinline__ uint32_t f2tf32(float x) {
    uint32_t r;
    asm("cvt.rna.tf32.f32 %0, %1;" : "=r"(r) : "f"(x));
    return r;
}
__device__ __forceinline__ void mma_tf32(float* d, const uint32_t* a, const uint32_t* b) {
    asm volatile(
        "mma.sync.aligned.m16n8k8.row.col.f32.tf32.tf32.f32 "
        "{%0,%1,%2,%3}, {%4,%5,%6,%7}, {%8,%9}, {%0,%1,%2,%3};\n"
        : "+f"(d[0]), "+f"(d[1]), "+f"(d[2]), "+f"(d[3])
        : "r"(a[0]), "r"(a[1]), "r"(a[2]), "r"(a[3]), "r"(b[0]), "r"(b[1]));
}
__device__ __forceinline__ void cp16(uint32_t dst, const void* src) {
    asm volatile("cp.async.cg.shared.global [%0], [%1], 16;" :: "r"(dst), "l"(src));
}

// ---------------- 1. merged preprocessing: pool+xpre3 | transW | convw ----------------
__global__ void __launch_bounds__(256) prep_k(const float* __restrict__ x,
                                              const float* __restrict__ W,
                                              const float* __restrict__ vw,
                                              const float* __restrict__ kw,
                                              const float* __restrict__ valw,
                                              const float* __restrict__ qw,
                                              const float* __restrict__ gqw,
                                              const float* __restrict__ gkw)
{
    __shared__ float ts[32][33];
    const int blk = blockIdx.x;
    if (blk < 256) {
        const int bg = blk;
        const int b = bg >> 5, g = bg & 31;
        const int c0 = g << 1;
        const float* xp0 = x + ((size_t)(b * CHN + c0)) * HW;
        const float* xp1 = xp0 + HW;
        uint32_t* pl0 = d_pooled_t + (size_t)(b * CHN + c0) * PIX;
        uint32_t* xpr3 = d_xpre3 + (size_t)bg * 3072;
        for (int p = threadIdx.x; p < PIX; p += 256) {
            const int h4 = p >> 5, w4 = p & 31;
            const int off = (h4 * 4) * 128 + w4 * 4;
            float s0 = 0.f, s1 = 0.f;
            #pragma unroll
            for (int i = 0; i < 4; i++) {
                float4 r0 = *(const float4*)(xp0 + off + i * 128);
                float4 r1 = *(const float4*)(xp1 + off + i * 128);
                s0 += r0.x + r0.y + r0.z + r0.w;
                s1 += r1.x + r1.y + r1.z + r1.w;
            }
            pl0[p]       = f2tf32(s0 * (1.f / 16.f));
            pl0[PIX + p] = f2tf32(s1 * (1.f / 16.f));
            const float xv = (s0 + s1) * (1.f / 32.f);
            const uint32_t hi = f2tf32(xv);
            const uint32_t lo = f2tf32(xv - __uint_as_float(hi));
            xpr3[p]        = hi;
            xpr3[1024 + p] = lo;
            xpr3[2048 + p] = hi;
        }
    } else if (blk < 1280) {
        const int bi = blk - 256;
        const int bx = bi & 31, by = bi >> 5;
        const int tx = threadIdx.x & 31, ty = threadIdx.x >> 5;
        #pragma unroll
        for (int r = ty; r < 32; r += 8)
            ts[r][tx] = W[(size_t)(by * 32 + r) * PIX + bx * 32 + tx];
        __syncthreads();
        #pragma unroll
        for (int r = ty; r < 32; r += 8)
            d_WT_t[(size_t)(bx * 32 + r) * PIX + by * 32 + tx] = f2tf32(ts[tx][r]);
    } else {
        const int i = (blk - 1280) * 256 + threadIdx.x;
        if (i < 1048576) {
            d_vw_t[i] = f2tf32(vw[i]);
        } else if (i < 1310720) {
            d_kw_t[i - 1048576] = f2tf32(kw[i - 1048576]);
        } else if (i < 2359296) {
            d_valw_t[i - 1310720] = f2tf32(valw[i - 1310720]);
        } else if (i < 2621440) {
            d_qw_t[i - 2359296] = f2tf32(qw[i - 2359296]);
        } else if (i < 2883584) {
            const int j = i - 2621440;
            const int r = j >> 10, c = j & 1023;
            const float xv = gqw[j];
            const uint32_t hi = f2tf32(xv);
            const uint32_t lo = f2tf32(xv - __uint_as_float(hi));
            d_qw3[(size_t)r * 3072 + c]        = hi;
            d_qw3[(size_t)r * 3072 + 1024 + c] = hi;
            d_qw3[(size_t)r * 3072 + 2048 + c] = lo;
        } else if (i < 3145728) {
            const int j = i - 2883584;
            const int r = j >> 10, c = j & 1023;
            const float xv = gkw[j];
            const uint32_t hi = f2tf32(xv);
            const uint32_t lo = f2tf32(xv - __uint_as_float(hi));
            d_kw3[(size_t)r * 3072 + c]        = hi;
            d_kw3[(size_t)r * 3072 + 1024 + c] = hi;
            d_kw3[(size_t)r * 3072 + 2048 + c] = lo;
        }
    }
}

// ---------------- 2. problem structs ----------------
struct GProb {
    const uint32_t* A; const uint32_t* B; float* Cp;
    int M, N, tm, tn, tile_begin, kch, lda, ldb;
};
struct GBatch { GProb p[4]; int n; };

// ---------------- 3. tf32 tensor-core GEMM (128x128, cp.async double-buffer) ----------------
__global__ void __launch_bounds__(256, 2) gemmtc_k(GBatch gb)
{
    extern __shared__ uint32_t sm[];
    uint32_t* Abuf = sm;
    uint32_t* Bbuf = sm + 2 * 128 * 36;

    const int bid = blockIdx.x;
    GProb pr = gb.p[0];
    #pragma unroll
    for (int i = 1; i < 4; i++)
        if (i < gb.n && bid >= gb.p[i].tile_begin) pr = gb.p[i];

    const int local = bid - pr.tile_begin;
    const int tmn = pr.tm * pr.tn;
    const int ks = local / tmn;
    const int t = local - ks * tmn;
    const int m0 = (t / pr.tn) << 7;
    const int n0 = (t % pr.tn) << 7;

    const int tid = threadIdx.x;
    const int lane = tid & 31;
    const int w = tid >> 5;
    const int wm = (w & 1) << 6;
    const int wn = (w >> 1) << 5;

    const int lrow = tid >> 1;
    const int lseg = (tid & 1) << 4;

    const uint32_t* Aptr = pr.A + (size_t)(m0 + lrow) * pr.lda + ks * pr.kch + lseg;
    const uint32_t* Bptr = pr.B + (size_t)(n0 + lrow) * pr.ldb + ks * pr.kch + lseg;
    const int nchunk = pr.kch >> 5;

    const uint32_t sa = (uint32_t)__cvta_generic_to_shared(&Abuf[lrow * 36 + lseg]);
    const uint32_t sb = (uint32_t)__cvta_generic_to_shared(&Bbuf[lrow * 36 + lseg]);
    const uint32_t bufstride = 128 * 36 * 4;

    float acc[4][4][4];
    #pragma unroll
    for (int i = 0; i < 4; i++)
        #pragma unroll
        for (int j = 0; j < 4; j++)
            #pragma unroll
            for (int q = 0; q < 4; q++) acc[i][j][q] = 0.f;

    const int fr = lane >> 2;
    const int fc = lane & 3;

    {
        cp16(sa, Aptr); cp16(sa + 16, Aptr + 4); cp16(sa + 32, Aptr + 8); cp16(sa + 48, Aptr + 12);
        cp16(sb, Bptr); cp16(sb + 16, Bptr + 4); cp16(sb + 32, Bptr + 8); cp16(sb + 48, Bptr + 12);
        asm volatile("cp.async.commit_group;");
    }

    for (int c = 0; c < nchunk; c++) {
        if (c + 1 < nchunk) {
            const uint32_t dsta = sa + ((c + 1) & 1) * bufstride;
            const uint32_t dstb = sb + ((c + 1) & 1) * bufstride;
            const uint32_t* ga = Aptr + (c + 1) * 32;
            const uint32_t* gb2 = Bptr + (c + 1) * 32;
            cp16(dsta, ga); cp16(dsta + 16, ga + 4); cp16(dsta + 32, ga + 8); cp16(dsta + 48, ga + 12);
            cp16(dstb, gb2); cp16(dstb + 16, gb2 + 4); cp16(dstb + 32, gb2 + 8); cp16(dstb + 48, gb2 + 12);
            asm volatile("cp.async.commit_group;");
            asm volatile("cp.async.wait_group 1;");
        } else {
            asm volatile("cp.async.wait_group 0;");
        }
        __syncthreads();

        const uint32_t* As = Abuf + (c & 1) * 128 * 36;
        const uint32_t* Bs = Bbuf + (c & 1) * 128 * 36;
        #pragma unroll
        for (int kst = 0; kst < 4; kst++) {
            const int k0 = kst << 3;
            uint32_t afr[4][4];
            #pragma unroll
            for (int mi = 0; mi < 4; mi++) {
                const int r0 = wm + (mi << 4) + fr;
                afr[mi][0] = As[r0 * 36 + k0 + fc];
                afr[mi][1] = As[(r0 + 8) * 36 + k0 + fc];
                afr[mi][2] = As[r0 * 36 + k0 + fc + 4];
                afr[mi][3] = As[(r0 + 8) * 36 + k0 + fc + 4];
            }
            uint32_t bfr[4][2];
            #pragma unroll
            for (int ni = 0; ni < 4; ni++) {
                const int cn = wn + (ni << 3) + fr;
                bfr[ni][0] = Bs[cn * 36 + k0 + fc];
                bfr[ni][1] = Bs[cn * 36 + k0 + fc + 4];
            }
            #pragma unroll
            for (int mi = 0; mi < 4; mi++)
                #pragma unroll
                for (int ni = 0; ni < 4; ni++)
                    mma_tf32(acc[mi][ni], afr[mi], bfr[ni]);
        }
        __syncthreads();
    }

    float* dst = pr.Cp + (size_t)ks * pr.M * pr.N;
    #pragma unroll
    for (int mi = 0; mi < 4; mi++) {
        const int mA = m0 + wm + (mi << 4) + fr;
        #pragma unroll
        for (int ni = 0; ni < 4; ni++) {
            const int n = n0 + wn + (ni << 3) + (fc << 1);
            *(float2*)(dst + (size_t)mA * pr.N + n)       = make_float2(acc[mi][ni][0], acc[mi][ni][1]);
            *(float2*)(dst + (size_t)(mA + 8) * pr.N + n) = make_float2(acc[mi][ni][2], acc[mi][ni][3]);
        }
    }
}

// ---------------- 4. split-K reduce + bias (gcnout + key) ----------------
struct RProb {
    const float* Cp; float* C; const float* bias; uint32_t* Ct;
    int MN4, N4, elem_begin, ksl;
};
struct RBatch { RProb p[4]; int n; int total; };

__global__ void __launch_bounds__(256) reduce_batch_k(RBatch rb)
{
    const int e = blockIdx.x * 256 + threadIdx.x;
    if (e >= rb.total) return;
    RProb pr = rb.p[0];
    #pragma unroll
    for (int i = 1; i < 4; i++)
        if (i < rb.n && e >= rb.p[i].elem_begin) pr = rb.p[i];
    const int local = e - pr.elem_begin;
    const int n4 = local % pr.N4;
    const float4* src = (const float4*)pr.Cp + local;
    float4 s = make_float4(0.f, 0.f, 0.f, 0.f);
    #pragma unroll 4
    for (int ks = 0; ks < pr.ksl; ks++) {
        float4 p = src[(size_t)ks * pr.MN4];
        s.x += p.x; s.y += p.y; s.z += p.z; s.w += p.w;
    }
    float4 bb = ((const float4*)pr.bias)[n4];
    s.x += bb.x; s.y += bb.y; s.z += bb.z; s.w += bb.w;
    ((float4*)pr.C)[local] = s;
    if (pr.Ct) {
        uint4 tv;
        tv.x = f2tf32(s.x); tv.y = f2tf32(s.y); tv.z = f2tf32(s.z); tv.w = f2tf32(s.w);
        ((uint4*)pr.Ct)[local] = tv;
    }
}

// ---------------- 5. fused adjav: reduce qg/kg (24) -> adj -> reduce v (8) -> av_t
// phase-1: qg @0 [24][65536], kg @1572864 [24][65536], v @3145728 [8][262144]
__global__ void __launch_bounds__(1024) adjav_k(const float* __restrict__ qb,
                                                const float* __restrict__ kb,
                                                const float* __restrict__ vb)
{
    extern __shared__ float smf[];
    float* qgS  = smf;                   // [32][257]
    float* kgS  = smf + 32 * 257;        // [32][257]
    float* adjS = smf + 2 * 32 * 257;    // [32][33]
    const int b = blockIdx.x;
    const int tid = threadIdx.x;

    for (int i = tid; i < 32 * 256; i += 1024) {
        const int s = i >> 8, d = i & 255;
        const int gidx = (b * 32 + s) * 256 + d;
        float sq = qb[d], sk = kb[d];
        #pragma unroll 8
        for (int ks = 0; ks < 24; ks++) {
            sq += d_part[ks * 65536 + gidx];
            sk += d_part[1572864 + ks * 65536 + gidx];
        }
        qgS[s * 257 + d] = sq;
        kgS[s * 257 + d] = sk;
    }
    __syncthreads();

    const int s = tid >> 5, t = tid & 31;
    {
        float acc = 0.f;
        #pragma unroll 8
        for (int d = 0; d < 256; d++)
            acc += kgS[s * 257 + d] * qgS[t * 257 + d];
        float m = wmax(acc);
        float e = expf(acc - m);
        float v = e / wsum(e);
        int rank = 0;
        #pragma unroll
        for (int j = 0; j < 32; j++) {
            float vj = __shfl_sync(0xffffffffu, v, j);
            rank += (vj > v) || (vj == v && j < t);
        }
        const bool keep = rank < KTOP;
        float v2 = keep ? v : -INFINITY;
        float m2 = wmax(v2);
        float e2 = keep ? expf(v - m2) : 0.f;
        float s2 = wsum(e2);
        adjS[s * 33 + t] = e2 / s2;
    }
    __syncthreads();

    const int p = tid;
    float vreg[32];
    #pragma unroll
    for (int g = 0; g < 32; g++) {
        float sv = vb[p];
        const int gidx = (b * 32 + g) * 1024 + p;
        #pragma unroll
        for (int ks = 0; ks < 8; ks++)
            sv += d_part[3145728 + ks * 262144 + gidx];
        vreg[g] = sv;
    }
    #pragma unroll 4
    for (int si = 0; si < 32; si++) {
        float acc = 0.f;
        #pragma unroll
        for (int g = 0; g < 32; g++) acc += adjS[si * 33 + g] * vreg[g];
        d_av_t[(size_t)(b * 32 + si) * 1024 + p] = f2tf32(acc);
    }
}

// ---------------- 6. fused attentu: atten (q2 16-slice reduce @4194304, key pre-reduced)
//                  + tu (value 16-slice reduce @0), grid (8,8)
__global__ void __launch_bounds__(256) attentu_k(const float* __restrict__ qb2,
                                                 const float* __restrict__ valb)
{
    extern __shared__ float smf[];
    float* attS = smf;                    // [64][33]
    float* Qs   = smf + 64 * 33;          // [32][257]
    float* vS   = Qs + 32 * 257;          // [32][128]
    const int b = blockIdx.x;
    const int p0 = blockIdx.y << 7;
    const int tid = threadIdx.x;

    // stage Qs (q2 = 16-slice reduce + bias)
    for (int i = tid; i < GRP * PQ; i += 256) {
        const int g = i >> 8, d = i & 255;
        float s = qb2[d];
        const int gidx = (b * 32 + g) * 256 + d;
        #pragma unroll
        for (int ks = 0; ks < 16; ks++)
            s += d_part[4194304 + ks * 65536 + gidx];
        Qs[g * 257 + d] = s;
    }
    // stage vS (value = 16-slice reduce + bias)
    for (int i = tid; i < GRP * 128; i += 256) {
        const int g = i >> 7, pp = i & 127;
        float s = valb[p0 + pp];
        const int gidx = (b * 32 + g) * 1024 + p0 + pp;
        #pragma unroll
        for (int ks = 0; ks < 16; ks++)
            s += d_part[ks * 262144 + gidx];
        vS[g * 128 + pp] = s;
    }
    __syncthreads();

    // atten: warp w -> channels w*8..w*8+7, lane = g
    const int w = tid >> 5, g = tid & 31;
    #pragma unroll
    for (int ci = 0; ci < 8; ci++) {
        const int c = w * 8 + ci;
        const float* krow = d_key + (size_t)(b * CHN + c) * PQ;
        float acc = 0.f;
        #pragma unroll 4
        for (int d = 0; d < PQ; d++)
            acc += __ldg(krow + d) * Qs[g * 257 + d];
        float m = wmax(acc);
        float e = expf(acc - m);
        attS[c * 33 + g] = e / wsum(e);
    }
    __syncthreads();

    // tu
    const int c = tid & 63;
    const int pr = tid >> 6;
    for (int pp = pr; pp < 128; pp += 4) {
        float acc = 0.f;
        #pragma unroll
        for (int g2 = 0; g2 < GRP; g2++) acc += attS[c * 33 + g2] * vS[g2 * 128 + pp];
        d_tuT[(size_t)b * 65536 + (size_t)(p0 + pp) * 64 + c] = acc;
    }
}

// ---------------- 7. Gram partials ----------------
__global__ void __launch_bounds__(256) gpart_k()
{
    __shared__ float Ts[128][65];
    const int b = blockIdx.x;
    const int k0 = blockIdx.y << 7;
    const int tid = threadIdx.x;
    for (int i = tid; i < 64 * 128; i += 256) {
        const int c = i >> 7, k = i & 127;
        Ts[k][c] = d_tuT[(size_t)b * 65536 + (size_t)c * 1024 + k0 + k];
    }
    __syncthreads();
    const int tx = tid & 15, ty = tid >> 4;
    float acc[4][4] = {};
    for (int k = 0; k < 128; k++) {
        float a0 = Ts[k][(ty << 2) + 0], a1 = Ts[k][(ty << 2) + 1];
        float a2 = Ts[k][(ty << 2) + 2], a3 = Ts[k][(ty << 2) + 3];
        float b0 = Ts[k][(tx << 2) + 0], b1 = Ts[k][(tx << 2) + 1];
        float b2 = Ts[k][(tx << 2) + 2], b3 = Ts[k][(tx << 2) + 3];
        acc[0][0] += a0 * b0; acc[0][1] += a0 * b1; acc[0][2] += a0 * b2; acc[0][3] += a0 * b3;
        acc[1][0] += a1 * b0; acc[1][1] += a1 * b1; acc[1][2] += a1 * b2; acc[1][3] += a1 * b3;
        acc[2][0] += a2 * b0; acc[2][1] += a2 * b1; acc[2][2] += a2 * b2; acc[2][3] += a2 * b3;
        acc[3][0] += a3 * b0; acc[3][1] += a3 * b1; acc[3][2] += a3 * b2; acc[3][3] += a3 * b3;
    }
    float* dst = d_Gpart + (size_t)(b * 8 + blockIdx.y) * 4096;
    #pragma unroll
    for (int i = 0; i < 4; i++)
        #pragma unroll
        for (int j = 0; j < 4; j++)
            dst[((ty << 2) + i) * 64 + (tx << 2) + j] = acc[i][j];
}

// ---------------- 8. out = G @ x_flat — tf32 tc, Gpart reduce fused into staging ----------------
__global__ void __launch_bounds__(256) finaltc_k(const float* __restrict__ x,
                                                 float* __restrict__ out)
{
    __shared__ uint32_t Gs[64][68];
    const int b = blockIdx.y;
    const int tid = threadIdx.x;
    const int lane = tid & 31, w = tid >> 5;
    const int fr = lane >> 2, fc = lane & 3;

    for (int i = tid; i < 4096; i += 256) {
        float s = 0.f;
        #pragma unroll
        for (int kc = 0; kc < 8; kc++)
            s += d_Gpart[(size_t)(b * 8 + kc) * 4096 + i];
        Gs[i >> 6][i & 63] = f2tf32(s);
    }
    __syncthreads();

    const int ng = (blockIdx.x << 8) + (w << 5);
    const float* xb = x + (size_t)b * CHN * HW;

    float acc[4][4][4];
    #pragma unroll
    for (int i = 0; i < 4; i++)
        #pragma unroll
        for (int j = 0; j < 4; j++)
            #pragma unroll
            for (int q = 0; q < 4; q++) acc[i][j][q] = 0.f;

    uint32_t bcur[4][2], bnxt[4][2];
    #pragma unroll
    for (int ni = 0; ni < 4; ni++) {
        const int n = ng + (ni << 3) + fr;
        bcur[ni][0] = f2tf32(__ldg(xb + (size_t)fc * HW + n));
        bcur[ni][1] = f2tf32(__ldg(xb + (size_t)(fc + 4) * HW + n));
        bnxt[ni][0] = 0; bnxt[ni][1] = 0;
    }

    #pragma unroll
    for (int kst = 0; kst < 8; kst++) {
        const int k0 = kst << 3;
        if (kst < 7) {
            #pragma unroll
            for (int ni = 0; ni < 4; ni++) {
                const int n = ng + (ni << 3) + fr;
                bnxt[ni][0] = f2tf32(__ldg(xb + (size_t)(k0 + 8 + fc) * HW + n));
                bnxt[ni][1] = f2tf32(__ldg(xb + (size_t)(k0 + 12 + fc) * HW + n));
            }
        }
        #pragma unroll
        for (int mi = 0; mi < 4; mi++) {
            uint32_t a[4];
            const int m0 = (mi << 4) + fr;
            a[0] = Gs[m0][k0 + fc];
            a[1] = Gs[m0 + 8][k0 + fc];
            a[2] = Gs[m0][k0 + fc + 4];
            a[3] = Gs[m0 + 8][k0 + fc + 4];
            #pragma unroll
            for (int ni = 0; ni < 4; ni++)
                mma_tf32(acc[mi][ni], a, bcur[ni]);
        }
        #pragma unroll
        for (int ni = 0; ni < 4; ni++) {
            bcur[ni][0] = bnxt[ni][0];
            bcur[ni][1] = bnxt[ni][1];
        }
    }

    float* ob = out + (size_t)b * CHN * HW;
    #pragma unroll
    for (int mi = 0; mi < 4; mi++) {
        const int m = (mi << 4) + fr;
        #pragma unroll
        for (int ni = 0; ni < 4; ni++) {
            const int n = ng + (ni << 3) + (fc << 1);
            *(float2*)(ob + (size_t)m * HW + n)       = make_float2(acc[mi][ni][0], acc[mi][ni][1]);
            *(float2*)(ob + (size_t)(m + 8) * HW + n) = make_float2(acc[mi][ni][2], acc[mi][ni][3]);
        }
    }
}

// ---------------- host launcher ----------------
extern "C" void kernel_launch(void* const* d_in, const int* in_sizes, int n_in,
                              void* d_out, int out_size)
{
    (void)in_sizes; (void)n_in; (void)out_size;
    const float* x          = (const float*)d_in[0];
    const float* gcn_weight = (const float*)d_in[1];
    const float* gcn_bias   = (const float*)d_in[2];
    const float* gcn_q_w    = (const float*)d_in[3];
    const float* gcn_q_b    = (const float*)d_in[4];
    const float* gcn_k_w    = (const float*)d_in[5];
    const float* gcn_k_b    = (const float*)d_in[6];
    const float* gcn_v_w    = (const float*)d_in[7];
    const float* gcn_v_b    = (const float*)d_in[8];
    const float* q_w        = (const float*)d_in[9];
    const float* q_b        = (const float*)d_in[10];
    const float* k_w        = (const float*)d_in[11];
    const float* k_b        = (const float*)d_in[12];
    const float* v_w        = (const float*)d_in[13];
    const float* v_b        = (const float*)d_in[14];
    float* out = (float*)d_out;

    float *p_part, *p_gcnout, *p_key;
    uint32_t *p_pooled_t, *p_xpre3, *p_WT_t, *p_vw_t, *p_kw_t, *p_valw_t, *p_qw_t,
             *p_qw3, *p_kw3, *p_av_t, *p_gcnout_t;
    cudaGetSymbolAddress((void**)&p_part,     d_part);
    cudaGetSymbolAddress((void**)&p_gcnout,   d_gcnout);
    cudaGetSymbolAddress((void**)&p_key,      d_key);
    cudaGetSymbolAddress((void**)&p_pooled_t, d_pooled_t);
    cudaGetSymbolAddress((void**)&p_xpre3,    d_xpre3);
    cudaGetSymbolAddress((void**)&p_WT_t,     d_WT_t);
    cudaGetSymbolAddress((void**)&p_vw_t,     d_vw_t);
    cudaGetSymbolAddress((void**)&p_kw_t,     d_kw_t);
    cudaGetSymbolAddress((void**)&p_valw_t,   d_valw_t);
    cudaGetSymbolAddress((void**)&p_qw_t,     d_qw_t);
    cudaGetSymbolAddress((void**)&p_qw3,      d_qw3);
    cudaGetSymbolAddress((void**)&p_kw3,      d_kw3);
    cudaGetSymbolAddress((void**)&p_av_t,     d_av_t);
    cudaGetSymbolAddress((void**)&p_gcnout_t, d_gcnout_t);

    cudaFuncSetAttribute(gemmtc_k, cudaFuncAttributeMaxDynamicSharedMemorySize, 73728);
    cudaFuncSetAttribute(adjav_k, cudaFuncAttributeMaxDynamicSharedMemorySize, 70016);
    cudaFuncSetAttribute(attentu_k, cudaFuncAttributeMaxDynamicSharedMemorySize, 60000);
    const int TCSMEM = 73728;
    const int AJSMEM = (2 * 32 * 257 + 32 * 33) * 4;
    const int ATSMEM = (64 * 33 + 32 * 257 + 32 * 128) * 4;

    // merged preprocessing
    prep_k<<<13568, 256>>>(x, gcn_weight, gcn_v_w, k_w, v_w, q_w, gcn_q_w, gcn_k_w);

    // ---- Phase 1: {qg3(ks24), kg3(ks24), v(ks8), key(ks8)} — uniform 4-chunk blocks ----
    {
        GBatch gb{};
        gb.p[0] = { p_xpre3,    p_qw3,  p_part + 0,       256, 256,  2, 2, 0,   128, 3072, 3072 };
        gb.p[1] = { p_xpre3,    p_kw3,  p_part + 1572864, 256, 256,  2, 2, 96,  128, 3072, 3072 };
        gb.p[2] = { p_xpre3,    p_vw_t, p_part + 3145728, 256, 1024, 2, 8, 192, 128, 3072, 1024 };
        gb.p[3] = { p_pooled_t, p_kw_t, p_part + 5242880, 512, 256,  4, 2, 320, 128, 1024, 1024 };
        gb.n = 4;
        gemmtc_k<<<384, 256, TCSMEM>>>(gb);
    }

    adjav_k<<<BATCH, 1024, AJSMEM>>>(gcn_q_b, gcn_k_b, gcn_v_b);

    // ---- Phase 2: gcnout = av @ WT, KS=16 (2-chunk blocks) -> 256 blocks ----
    {
        GBatch gb{};
        gb.p[0] = { p_av_t, p_WT_t, p_part, 256, 1024, 2, 8, 0, 64, 1024, 1024 };
        gb.n = 1;
        gemmtc_k<<<2 * 8 * 16, 256, TCSMEM>>>(gb);

        // reduce gcnout (16 slices @0) + key (8 slices @5242880, from phase-1)
        RBatch rb{};
        rb.p[0] = { p_part,           p_gcnout, gcn_bias, p_gcnout_t, 256 * 1024 / 4, 1024 / 4, 0,     16 };
        rb.p[1] = { p_part + 5242880, p_key,    k_b,      nullptr,    512 * 256 / 4,  256 / 4,  65536, 8 };
        rb.n = 2; rb.total = 65536 + 32768;
        reduce_batch_k<<<(rb.total + 255) / 256, 256>>>(rb);
    }

    // ---- Phase 3: {value(ks16), q2(ks16)} — 2-chunk blocks, 320 blocks ----
    {
        GBatch gb{};
        gb.p[0] = { p_gcnout_t, p_valw_t, p_part + 0,       256, 1024, 2, 8, 0,   64, 1024, 1024 };
        gb.p[1] = { p_gcnout_t, p_qw_t,   p_part + 4194304, 256, 256,  2, 2, 256, 64, 1024, 1024 };
        gb.n = 2;
        gemmtc_k<<<320, 256, TCSMEM>>>(gb);
    }

    attentu_k<<<dim3(BATCH, 8), 256, ATSMEM>>>(q_b, v_b);
    gpart_k<<<dim3(BATCH, 8), 256>>>();
    finaltc_k<<<dim3(64, BATCH), 256>>>(x, out);
}

// round 14
// speedup vs baseline: 1.2878x; 1.2878x over previous
#include <cuda_runtime.h>
#include <math.h>
#include <stdint.h>

// Problem constants
#define BATCH 8
#define CHN   64
#define PIX   1024
#define PQ    256
#define GRP   32
#define HW    16384   // 128*128
#define KTOP  21      // int(32/3*2)

// ---------------- scratch (static device globals; no allocation) ----------------
__device__ uint32_t d_pooled_t[BATCH*CHN*PIX];   // tf32
__device__ uint32_t d_xpre3  [256*3072];         // [hi | lo | hi] per row
__device__ uint32_t d_WT_t   [PIX*PIX];          // gcn_weight^T tf32
__device__ uint32_t d_vw_t   [PIX*PIX];          // gcn_v_w tf32
__device__ uint32_t d_kw_t   [PQ*PIX];           // k_w tf32
__device__ uint32_t d_valw_t [PIX*PIX];          // v_w tf32
__device__ uint32_t d_qw_t   [PQ*PIX];           // q_w tf32
__device__ uint32_t d_qw3    [PQ*3072];          // gcn_q_w [hi | hi | lo]
__device__ uint32_t d_kw3    [PQ*3072];          // gcn_k_w [hi | hi | lo]
__device__ uint32_t d_av_t   [BATCH*GRP*PIX];    // tf32
__device__ float    d_gcnout [BATCH*GRP*PIX];
__device__ uint32_t d_gcnout_t[BATCH*GRP*PIX];   // tf32
__device__ float d_key   [BATCH*CHN*PQ];         // reduced key (phase-2 reduce)
__device__ float d_atten [BATCH*CHN*GRP];
__device__ float d_tuT   [BATCH*PIX*CHN];
__device__ float d_Gpart [BATCH*8*CHN*CHN];
__device__ float d_part  [8388608];              // split-K partials (32 MB)

// ---------------- helpers ----------------
__device__ __forceinline__ float wmax(float v) {
    #pragma unroll
    for (int o = 16; o > 0; o >>= 1) v = fmaxf(v, __shfl_xor_sync(0xffffffffu, v, o));
    return v;
}
__device__ __forceinline__ float wsum(float v) {
    #pragma unroll
    for (int o = 16; o > 0; o >>= 1) v += __shfl_xor_sync(0xffffffffu, v, o);
    return v;
}
__device__ __forceinline__ uint32_t f2tf32(float x) {
    uint32_t r;
    asm("cvt.rna.tf32.f32 %0, %1;" : "=r"(r) : "f"(x));
    return r;
}
__device__ __forceinline__ void mma_tf32(float* d, const uint32_t* a, const uint32_t* b) {
    asm volatile(
        "mma.sync.aligned.m16n8k8.row.col.f32.tf32.tf32.f32 "
        "{%0,%1,%2,%3}, {%4,%5,%6,%7}, {%8,%9}, {%0,%1,%2,%3};\n"
        : "+f"(d[0]), "+f"(d[1]), "+f"(d[2]), "+f"(d[3])
        : "r"(a[0]), "r"(a[1]), "r"(a[2]), "r"(a[3]), "r"(b[0]), "r"(b[1]));
}
__device__ __forceinline__ void cp16(uint32_t dst, const void* src) {
    asm volatile("cp.async.cg.shared.global [%0], [%1], 16;" :: "r"(dst), "l"(src));
}

// ---------------- 1. merged preprocessing: pool+xpre3 | transW | convw ----------------
__global__ void __launch_bounds__(256) prep_k(const float* __restrict__ x,
                                              const float* __restrict__ W,
                                              const float* __restrict__ vw,
                                              const float* __restrict__ kw,
                                              const float* __restrict__ valw,
                                              const float* __restrict__ qw,
                                              const float* __restrict__ gqw,
                                              const float* __restrict__ gkw)
{
    __shared__ float ts[32][33];
    const int blk = blockIdx.x;
    if (blk < 256) {
        const int bg = blk;
        const int b = bg >> 5, g = bg & 31;
        const int c0 = g << 1;
        const float* xp0 = x + ((size_t)(b * CHN + c0)) * HW;
        const float* xp1 = xp0 + HW;
        uint32_t* pl0 = d_pooled_t + (size_t)(b * CHN + c0) * PIX;
        uint32_t* xpr3 = d_xpre3 + (size_t)bg * 3072;
        for (int p = threadIdx.x; p < PIX; p += 256) {
            const int h4 = p >> 5, w4 = p & 31;
            const int off = (h4 * 4) * 128 + w4 * 4;
            float s0 = 0.f, s1 = 0.f;
            #pragma unroll
            for (int i = 0; i < 4; i++) {
                float4 r0 = *(const float4*)(xp0 + off + i * 128);
                float4 r1 = *(const float4*)(xp1 + off + i * 128);
                s0 += r0.x + r0.y + r0.z + r0.w;
                s1 += r1.x + r1.y + r1.z + r1.w;
            }
            pl0[p]       = f2tf32(s0 * (1.f / 16.f));
            pl0[PIX + p] = f2tf32(s1 * (1.f / 16.f));
            const float xv = (s0 + s1) * (1.f / 32.f);
            const uint32_t hi = f2tf32(xv);
            const uint32_t lo = f2tf32(xv - __uint_as_float(hi));
            xpr3[p]        = hi;
            xpr3[1024 + p] = lo;
            xpr3[2048 + p] = hi;
        }
    } else if (blk < 1280) {
        const int bi = blk - 256;
        const int bx = bi & 31, by = bi >> 5;
        const int tx = threadIdx.x & 31, ty = threadIdx.x >> 5;
        #pragma unroll
        for (int r = ty; r < 32; r += 8)
            ts[r][tx] = W[(size_t)(by * 32 + r) * PIX + bx * 32 + tx];
        __syncthreads();
        #pragma unroll
        for (int r = ty; r < 32; r += 8)
            d_WT_t[(size_t)(bx * 32 + r) * PIX + by * 32 + tx] = f2tf32(ts[tx][r]);
    } else {
        const int i = (blk - 1280) * 256 + threadIdx.x;
        if (i < 1048576) {
            d_vw_t[i] = f2tf32(vw[i]);
        } else if (i < 1310720) {
            d_kw_t[i - 1048576] = f2tf32(kw[i - 1048576]);
        } else if (i < 2359296) {
            d_valw_t[i - 1310720] = f2tf32(valw[i - 1310720]);
        } else if (i < 2621440) {
            d_qw_t[i - 2359296] = f2tf32(qw[i - 2359296]);
        } else if (i < 2883584) {
            const int j = i - 2621440;
            const int r = j >> 10, c = j & 1023;
            const float xv = gqw[j];
            const uint32_t hi = f2tf32(xv);
            const uint32_t lo = f2tf32(xv - __uint_as_float(hi));
            d_qw3[(size_t)r * 3072 + c]        = hi;
            d_qw3[(size_t)r * 3072 + 1024 + c] = hi;
            d_qw3[(size_t)r * 3072 + 2048 + c] = lo;
        } else if (i < 3145728) {
            const int j = i - 2883584;
            const int r = j >> 10, c = j & 1023;
            const float xv = gkw[j];
            const uint32_t hi = f2tf32(xv);
            const uint32_t lo = f2tf32(xv - __uint_as_float(hi));
            d_kw3[(size_t)r * 3072 + c]        = hi;
            d_kw3[(size_t)r * 3072 + 1024 + c] = hi;
            d_kw3[(size_t)r * 3072 + 2048 + c] = lo;
        }
    }
}

// ---------------- 2. problem structs ----------------
struct GProb {
    const uint32_t* A; const uint32_t* B; float* Cp;
    int M, N, tm, tn, tile_begin, kch, lda, ldb;
};
struct GBatch { GProb p[4]; int n; };

// ---------------- 3. tf32 tensor-core GEMM (128x128, cp.async double-buffer) ----------------
__global__ void __launch_bounds__(256, 2) gemmtc_k(GBatch gb)
{
    extern __shared__ uint32_t sm[];
    uint32_t* Abuf = sm;
    uint32_t* Bbuf = sm + 2 * 128 * 36;

    const int bid = blockIdx.x;
    GProb pr = gb.p[0];
    #pragma unroll
    for (int i = 1; i < 4; i++)
        if (i < gb.n && bid >= gb.p[i].tile_begin) pr = gb.p[i];

    const int local = bid - pr.tile_begin;
    const int tmn = pr.tm * pr.tn;
    const int ks = local / tmn;
    const int t = local - ks * tmn;
    const int m0 = (t / pr.tn) << 7;
    const int n0 = (t % pr.tn) << 7;

    const int tid = threadIdx.x;
    const int lane = tid & 31;
    const int w = tid >> 5;
    const int wm = (w & 1) << 6;
    const int wn = (w >> 1) << 5;

    const int lrow = tid >> 1;
    const int lseg = (tid & 1) << 4;

    const uint32_t* Aptr = pr.A + (size_t)(m0 + lrow) * pr.lda + ks * pr.kch + lseg;
    const uint32_t* Bptr = pr.B + (size_t)(n0 + lrow) * pr.ldb + ks * pr.kch + lseg;
    const int nchunk = pr.kch >> 5;

    const uint32_t sa = (uint32_t)__cvta_generic_to_shared(&Abuf[lrow * 36 + lseg]);
    const uint32_t sb = (uint32_t)__cvta_generic_to_shared(&Bbuf[lrow * 36 + lseg]);
    const uint32_t bufstride = 128 * 36 * 4;

    float acc[4][4][4];
    #pragma unroll
    for (int i = 0; i < 4; i++)
        #pragma unroll
        for (int j = 0; j < 4; j++)
            #pragma unroll
            for (int q = 0; q < 4; q++) acc[i][j][q] = 0.f;

    const int fr = lane >> 2;
    const int fc = lane & 3;

    {
        cp16(sa, Aptr); cp16(sa + 16, Aptr + 4); cp16(sa + 32, Aptr + 8); cp16(sa + 48, Aptr + 12);
        cp16(sb, Bptr); cp16(sb + 16, Bptr + 4); cp16(sb + 32, Bptr + 8); cp16(sb + 48, Bptr + 12);
        asm volatile("cp.async.commit_group;");
    }

    for (int c = 0; c < nchunk; c++) {
        if (c + 1 < nchunk) {
            const uint32_t dsta = sa + ((c + 1) & 1) * bufstride;
            const uint32_t dstb = sb + ((c + 1) & 1) * bufstride;
            const uint32_t* ga = Aptr + (c + 1) * 32;
            const uint32_t* gb2 = Bptr + (c + 1) * 32;
            cp16(dsta, ga); cp16(dsta + 16, ga + 4); cp16(dsta + 32, ga + 8); cp16(dsta + 48, ga + 12);
            cp16(dstb, gb2); cp16(dstb + 16, gb2 + 4); cp16(dstb + 32, gb2 + 8); cp16(dstb + 48, gb2 + 12);
            asm volatile("cp.async.commit_group;");
            asm volatile("cp.async.wait_group 1;");
        } else {
            asm volatile("cp.async.wait_group 0;");
        }
        __syncthreads();

        const uint32_t* As = Abuf + (c & 1) * 128 * 36;
        const uint32_t* Bs = Bbuf + (c & 1) * 128 * 36;
        #pragma unroll
        for (int kst = 0; kst < 4; kst++) {
            const int k0 = kst << 3;
            uint32_t afr[4][4];
            #pragma unroll
            for (int mi = 0; mi < 4; mi++) {
                const int r0 = wm + (mi << 4) + fr;
                afr[mi][0] = As[r0 * 36 + k0 + fc];
                afr[mi][1] = As[(r0 + 8) * 36 + k0 + fc];
                afr[mi][2] = As[r0 * 36 + k0 + fc + 4];
                afr[mi][3] = As[(r0 + 8) * 36 + k0 + fc + 4];
            }
            uint32_t bfr[4][2];
            #pragma unroll
            for (int ni = 0; ni < 4; ni++) {
                const int cn = wn + (ni << 3) + fr;
                bfr[ni][0] = Bs[cn * 36 + k0 + fc];
                bfr[ni][1] = Bs[cn * 36 + k0 + fc + 4];
            }
            #pragma unroll
            for (int mi = 0; mi < 4; mi++)
                #pragma unroll
                for (int ni = 0; ni < 4; ni++)
                    mma_tf32(acc[mi][ni], afr[mi], bfr[ni]);
        }
        __syncthreads();
    }

    float* dst = pr.Cp + (size_t)ks * pr.M * pr.N;
    #pragma unroll
    for (int mi = 0; mi < 4; mi++) {
        const int mA = m0 + wm + (mi << 4) + fr;
        #pragma unroll
        for (int ni = 0; ni < 4; ni++) {
            const int n = n0 + wn + (ni << 3) + (fc << 1);
            *(float2*)(dst + (size_t)mA * pr.N + n)       = make_float2(acc[mi][ni][0], acc[mi][ni][1]);
            *(float2*)(dst + (size_t)(mA + 8) * pr.N + n) = make_float2(acc[mi][ni][2], acc[mi][ni][3]);
        }
    }
}

// ---------------- 4. split-K reduce + bias (gcnout + key) ----------------
struct RProb {
    const float* Cp; float* C; const float* bias; uint32_t* Ct;
    int MN4, N4, elem_begin, ksl;
};
struct RBatch { RProb p[4]; int n; int total; };

__global__ void __launch_bounds__(256) reduce_batch_k(RBatch rb)
{
    const int e = blockIdx.x * 256 + threadIdx.x;
    if (e >= rb.total) return;
    RProb pr = rb.p[0];
    #pragma unroll
    for (int i = 1; i < 4; i++)
        if (i < rb.n && e >= rb.p[i].elem_begin) pr = rb.p[i];
    const int local = e - pr.elem_begin;
    const int n4 = local % pr.N4;
    const float4* src = (const float4*)pr.Cp + local;
    float4 s = make_float4(0.f, 0.f, 0.f, 0.f);
    #pragma unroll 4
    for (int ks = 0; ks < pr.ksl; ks++) {
        float4 p = src[(size_t)ks * pr.MN4];
        s.x += p.x; s.y += p.y; s.z += p.z; s.w += p.w;
    }
    float4 bb = ((const float4*)pr.bias)[n4];
    s.x += bb.x; s.y += bb.y; s.z += bb.z; s.w += bb.w;
    ((float4*)pr.C)[local] = s;
    if (pr.Ct) {
        uint4 tv;
        tv.x = f2tf32(s.x); tv.y = f2tf32(s.y); tv.z = f2tf32(s.z); tv.w = f2tf32(s.w);
        ((uint4*)pr.Ct)[local] = tv;
    }
}

// ---------------- 5. fused adjav: reduce qg/kg (24) -> adj -> reduce v (8) -> av_t
// phase-1: qg @0 [24][65536], kg @1572864 [24][65536], v @3145728 [8][262144]
__global__ void __launch_bounds__(1024) adjav_k(const float* __restrict__ qb,
                                                const float* __restrict__ kb,
                                                const float* __restrict__ vb)
{
    extern __shared__ float smf[];
    float* qgS  = smf;                   // [32][257]
    float* kgS  = smf + 32 * 257;        // [32][257]
    float* adjS = smf + 2 * 32 * 257;    // [32][33]
    const int b = blockIdx.x;
    const int tid = threadIdx.x;

    for (int i = tid; i < 32 * 256; i += 1024) {
        const int s = i >> 8, d = i & 255;
        const int gidx = (b * 32 + s) * 256 + d;
        float sq = qb[d], sk = kb[d];
        #pragma unroll 8
        for (int ks = 0; ks < 24; ks++) {
            sq += d_part[ks * 65536 + gidx];
            sk += d_part[1572864 + ks * 65536 + gidx];
        }
        qgS[s * 257 + d] = sq;
        kgS[s * 257 + d] = sk;
    }
    __syncthreads();

    const int s = tid >> 5, t = tid & 31;
    {
        float acc = 0.f;
        #pragma unroll 8
        for (int d = 0; d < 256; d++)
            acc += kgS[s * 257 + d] * qgS[t * 257 + d];
        float m = wmax(acc);
        float e = expf(acc - m);
        float v = e / wsum(e);
        int rank = 0;
        #pragma unroll
        for (int j = 0; j < 32; j++) {
            float vj = __shfl_sync(0xffffffffu, v, j);
            rank += (vj > v) || (vj == v && j < t);
        }
        const bool keep = rank < KTOP;
        float v2 = keep ? v : -INFINITY;
        float m2 = wmax(v2);
        float e2 = keep ? expf(v - m2) : 0.f;
        float s2 = wsum(e2);
        adjS[s * 33 + t] = e2 / s2;
    }
    __syncthreads();

    const int p = tid;
    float vreg[32];
    #pragma unroll
    for (int g = 0; g < 32; g++) {
        float sv = vb[p];
        const int gidx = (b * 32 + g) * 1024 + p;
        #pragma unroll
        for (int ks = 0; ks < 8; ks++)
            sv += d_part[3145728 + ks * 262144 + gidx];
        vreg[g] = sv;
    }
    #pragma unroll 4
    for (int si = 0; si < 32; si++) {
        float acc = 0.f;
        #pragma unroll
        for (int g = 0; g < 32; g++) acc += adjS[si * 33 + g] * vreg[g];
        d_av_t[(size_t)(b * 32 + si) * 1024 + p] = f2tf32(acc);
    }
}

// ---------------- 6. atten: q2 8-slice reduce @2097152, key pre-reduced ----------------
__global__ void __launch_bounds__(256) atten_k(const float* __restrict__ qb2)
{
    __shared__ float Qs[GRP][PQ + 4];
    const int b = blockIdx.x;
    const int cg = blockIdx.y;
    const int tid = threadIdx.x;
    for (int i = tid; i < GRP * PQ; i += 256) {
        const int g = i >> 8, d = i & 255;
        float s = qb2[d];
        const int gidx = (b * 32 + g) * 256 + d;
        #pragma unroll
        for (int ks = 0; ks < 8; ks++)
            s += d_part[2097152 + ks * 65536 + gidx];
        Qs[g][d] = s;
    }
    __syncthreads();
    const int w = tid >> 5, g = tid & 31;
    const int c = cg * 8 + w;
    const float* krow = d_key + (size_t)(b * CHN + c) * PQ;
    float acc = 0.f;
    #pragma unroll 4
    for (int d = 0; d < PQ; d++)
        acc += __ldg(krow + d) * Qs[g][d];
    float m = wmax(acc);
    float e = expf(acc - m);
    d_atten[(b * CHN + c) * GRP + g] = e / wsum(e);
}

// ---------------- 7. tu = atten @ value (value partials @0, 8 slices) ----------------
__global__ void __launch_bounds__(256) tu_k(const float* __restrict__ valb)
{
    __shared__ float attS[CHN][GRP + 1];
    __shared__ float vS[GRP][128];
    const int b = blockIdx.x;
    const int p0 = blockIdx.y << 7;
    const int tid = threadIdx.x;
    for (int i = tid; i < CHN * GRP; i += 256)
        attS[i >> 5][i & 31] = d_atten[b * CHN * GRP + i];
    for (int i = tid; i < GRP * 128; i += 256) {
        const int g = i >> 7, pp = i & 127;
        float s = valb[p0 + pp];
        const int gidx = (b * 32 + g) * 1024 + p0 + pp;
        #pragma unroll
        for (int ks = 0; ks < 8; ks++)
            s += d_part[ks * 262144 + gidx];
        vS[g][pp] = s;
    }
    __syncthreads();
    const int c = tid & 63;
    const int pr = tid >> 6;
    for (int pp = pr; pp < 128; pp += 4) {
        float acc = 0.f;
        #pragma unroll
        for (int g = 0; g < GRP; g++) acc += attS[c][g] * vS[g][pp];
        d_tuT[(size_t)b * 65536 + (size_t)(p0 + pp) * 64 + c] = acc;
    }
}

// ---------------- 8. Gram partials ----------------
__global__ void __launch_bounds__(256) gpart_k()
{
    __shared__ float Ts[128][65];
    const int b = blockIdx.x;
    const int k0 = blockIdx.y << 7;
    const int tid = threadIdx.x;
    for (int i = tid; i < 64 * 128; i += 256) {
        const int c = i >> 7, k = i & 127;
        Ts[k][c] = d_tuT[(size_t)b * 65536 + (size_t)c * 1024 + k0 + k];
    }
    __syncthreads();
    const int tx = tid & 15, ty = tid >> 4;
    float acc[4][4] = {};
    for (int k = 0; k < 128; k++) {
        float a0 = Ts[k][(ty << 2) + 0], a1 = Ts[k][(ty << 2) + 1];
        float a2 = Ts[k][(ty << 2) + 2], a3 = Ts[k][(ty << 2) + 3];
        float b0 = Ts[k][(tx << 2) + 0], b1 = Ts[k][(tx << 2) + 1];
        float b2 = Ts[k][(tx << 2) + 2], b3 = Ts[k][(tx << 2) + 3];
        acc[0][0] += a0 * b0; acc[0][1] += a0 * b1; acc[0][2] += a0 * b2; acc[0][3] += a0 * b3;
        acc[1][0] += a1 * b0; acc[1][1] += a1 * b1; acc[1][2] += a1 * b2; acc[1][3] += a1 * b3;
        acc[2][0] += a2 * b0; acc[2][1] += a2 * b1; acc[2][2] += a2 * b2; acc[2][3] += a2 * b3;
        acc[3][0] += a3 * b0; acc[3][1] += a3 * b1; acc[3][2] += a3 * b2; acc[3][3] += a3 * b3;
    }
    float* dst = d_Gpart + (size_t)(b * 8 + blockIdx.y) * 4096;
    #pragma unroll
    for (int i = 0; i < 4; i++)
        #pragma unroll
        for (int j = 0; j < 4; j++)
            dst[((ty << 2) + i) * 64 + (tx << 2) + j] = acc[i][j];
}

// ---------------- 9. out = G @ x_flat — tf32 tc, Gpart reduce fused into staging ----------------
__global__ void __launch_bounds__(256) finaltc_k(const float* __restrict__ x,
                                                 float* __restrict__ out)
{
    __shared__ uint32_t Gs[64][68];
    const int b = blockIdx.y;
    const int tid = threadIdx.x;
    const int lane = tid & 31, w = tid >> 5;
    const int fr = lane >> 2, fc = lane & 3;

    for (int i = tid; i < 4096; i += 256) {
        float s = 0.f;
        #pragma unroll
        for (int kc = 0; kc < 8; kc++)
            s += d_Gpart[(size_t)(b * 8 + kc) * 4096 + i];
        Gs[i >> 6][i & 63] = f2tf32(s);
    }
    __syncthreads();

    const int ng = (blockIdx.x << 8) + (w << 5);
    const float* xb = x + (size_t)b * CHN * HW;

    float acc[4][4][4];
    #pragma unroll
    for (int i = 0; i < 4; i++)
        #pragma unroll
        for (int j = 0; j < 4; j++)
            #pragma unroll
            for (int q = 0; q < 4; q++) acc[i][j][q] = 0.f;

    uint32_t bcur[4][2], bnxt[4][2];
    #pragma unroll
    for (int ni = 0; ni < 4; ni++) {
        const int n = ng + (ni << 3) + fr;
        bcur[ni][0] = f2tf32(__ldg(xb + (size_t)fc * HW + n));
        bcur[ni][1] = f2tf32(__ldg(xb + (size_t)(fc + 4) * HW + n));
        bnxt[ni][0] = 0; bnxt[ni][1] = 0;
    }

    #pragma unroll
    for (int kst = 0; kst < 8; kst++) {
        const int k0 = kst << 3;
        if (kst < 7) {
            #pragma unroll
            for (int ni = 0; ni < 4; ni++) {
                const int n = ng + (ni << 3) + fr;
                bnxt[ni][0] = f2tf32(__ldg(xb + (size_t)(k0 + 8 + fc) * HW + n));
                bnxt[ni][1] = f2tf32(__ldg(xb + (size_t)(k0 + 12 + fc) * HW + n));
            }
        }
        #pragma unroll
        for (int mi = 0; mi < 4; mi++) {
            uint32_t a[4];
            const int m0 = (mi << 4) + fr;
            a[0] = Gs[m0][k0 + fc];
            a[1] = Gs[m0 + 8][k0 + fc];
            a[2] = Gs[m0][k0 + fc + 4];
            a[3] = Gs[m0 + 8][k0 + fc + 4];
            #pragma unroll
            for (int ni = 0; ni < 4; ni++)
                mma_tf32(acc[mi][ni], a, bcur[ni]);
        }
        #pragma unroll
        for (int ni = 0; ni < 4; ni++) {
            bcur[ni][0] = bnxt[ni][0];
            bcur[ni][1] = bnxt[ni][1];
        }
    }

    float* ob = out + (size_t)b * CHN * HW;
    #pragma unroll
    for (int mi = 0; mi < 4; mi++) {
        const int m = (mi << 4) + fr;
        #pragma unroll
        for (int ni = 0; ni < 4; ni++) {
            const int n = ng + (ni << 3) + (fc << 1);
            *(float2*)(ob + (size_t)m * HW + n)       = make_float2(acc[mi][ni][0], acc[mi][ni][1]);
            *(float2*)(ob + (size_t)(m + 8) * HW + n) = make_float2(acc[mi][ni][2], acc[mi][ni][3]);
        }
    }
}

// ---------------- host launcher ----------------
extern "C" void kernel_launch(void* const* d_in, const int* in_sizes, int n_in,
                              void* d_out, int out_size)
{
    (void)in_sizes; (void)n_in; (void)out_size;
    const float* x          = (const float*)d_in[0];
    const float* gcn_weight = (const float*)d_in[1];
    const float* gcn_bias   = (const float*)d_in[2];
    const float* gcn_q_w    = (const float*)d_in[3];
    const float* gcn_q_b    = (const float*)d_in[4];
    const float* gcn_k_w    = (const float*)d_in[5];
    const float* gcn_k_b    = (const float*)d_in[6];
    const float* gcn_v_w    = (const float*)d_in[7];
    const float* gcn_v_b    = (const float*)d_in[8];
    const float* q_w        = (const float*)d_in[9];
    const float* q_b        = (const float*)d_in[10];
    const float* k_w        = (const float*)d_in[11];
    const float* k_b        = (const float*)d_in[12];
    const float* v_w        = (const float*)d_in[13];
    const float* v_b        = (const float*)d_in[14];
    float* out = (float*)d_out;

    float *p_part, *p_gcnout, *p_key;
    uint32_t *p_pooled_t, *p_xpre3, *p_WT_t, *p_vw_t, *p_kw_t, *p_valw_t, *p_qw_t,
             *p_qw3, *p_kw3, *p_av_t, *p_gcnout_t;
    cudaGetSymbolAddress((void**)&p_part,     d_part);
    cudaGetSymbolAddress((void**)&p_gcnout,   d_gcnout);
    cudaGetSymbolAddress((void**)&p_key,      d_key);
    cudaGetSymbolAddress((void**)&p_pooled_t, d_pooled_t);
    cudaGetSymbolAddress((void**)&p_xpre3,    d_xpre3);
    cudaGetSymbolAddress((void**)&p_WT_t,     d_WT_t);
    cudaGetSymbolAddress((void**)&p_vw_t,     d_vw_t);
    cudaGetSymbolAddress((void**)&p_kw_t,     d_kw_t);
    cudaGetSymbolAddress((void**)&p_valw_t,   d_valw_t);
    cudaGetSymbolAddress((void**)&p_qw_t,     d_qw_t);
    cudaGetSymbolAddress((void**)&p_qw3,      d_qw3);
    cudaGetSymbolAddress((void**)&p_kw3,      d_kw3);
    cudaGetSymbolAddress((void**)&p_av_t,     d_av_t);
    cudaGetSymbolAddress((void**)&p_gcnout_t, d_gcnout_t);

    cudaFuncSetAttribute(gemmtc_k, cudaFuncAttributeMaxDynamicSharedMemorySize, 73728);
    cudaFuncSetAttribute(adjav_k, cudaFuncAttributeMaxDynamicSharedMemorySize, 70016);
    const int TCSMEM = 73728;
    const int AJSMEM = (2 * 32 * 257 + 32 * 33) * 4;

    // merged preprocessing
    prep_k<<<13568, 256>>>(x, gcn_weight, gcn_v_w, k_w, v_w, q_w, gcn_q_w, gcn_k_w);

    // ---- Phase 1: {qg3(ks24), kg3(ks24), v(ks8), key(ks8)} — uniform 4-chunk blocks ----
    {
        GBatch gb{};
        gb.p[0] = { p_xpre3,    p_qw3,  p_part + 0,       256, 256,  2, 2, 0,   128, 3072, 3072 };
        gb.p[1] = { p_xpre3,    p_kw3,  p_part + 1572864, 256, 256,  2, 2, 96,  128, 3072, 3072 };
        gb.p[2] = { p_xpre3,    p_vw_t, p_part + 3145728, 256, 1024, 2, 8, 192, 128, 3072, 1024 };
        gb.p[3] = { p_pooled_t, p_kw_t, p_part + 5242880, 512, 256,  4, 2, 320, 128, 1024, 1024 };
        gb.n = 4;
        gemmtc_k<<<384, 256, TCSMEM>>>(gb);
    }

    adjav_k<<<BATCH, 1024, AJSMEM>>>(gcn_q_b, gcn_k_b, gcn_v_b);

    // ---- Phase 2: gcnout = av @ WT, KS=8 -> 128 blocks; reduce gcnout + key ----
    {
        GBatch gb{};
        gb.p[0] = { p_av_t, p_WT_t, p_part, 256, 1024, 2, 8, 0, 128, 1024, 1024 };
        gb.n = 1;
        gemmtc_k<<<2 * 8 * 8, 256, TCSMEM>>>(gb);

        RBatch rb{};
        rb.p[0] = { p_part,           p_gcnout, gcn_bias, p_gcnout_t, 256 * 1024 / 4, 1024 / 4, 0,     8 };
        rb.p[1] = { p_part + 5242880, p_key,    k_b,      nullptr,    512 * 256 / 4,  256 / 4,  65536, 8 };
        rb.n = 2; rb.total = 65536 + 32768;
        reduce_batch_k<<<(rb.total + 255) / 256, 256>>>(rb);
    }

    // ---- Phase 3: {value(ks8), q2(ks8)} — 160 blocks ----
    {
        GBatch gb{};
        gb.p[0] = { p_gcnout_t, p_valw_t, p_part + 0,       256, 1024, 2, 8, 0,   128, 1024, 1024 };
        gb.p[1] = { p_gcnout_t, p_qw_t,   p_part + 2097152, 256, 256,  2, 2, 128, 128, 1024, 1024 };
        gb.n = 2;
        gemmtc_k<<<160, 256, TCSMEM>>>(gb);
    }

    atten_k<<<dim3(BATCH, 8), 256>>>(q_b);
    tu_k<<<dim3(BATCH, 8), 256>>>(v_b);
    gpart_k<<<dim3(BATCH, 8), 256>>>();
    finaltc_k<<<dim3(64, BATCH), 256>>>(x, out);
}

// round 15
// speedup vs baseline: 1.3333x; 1.0354x over previous
#include <cuda_runtime.h>
#include <math.h>
#include <stdint.h>

// Problem constants
#define BATCH 8
#define CHN   64
#define PIX   1024
#define PQ    256
#define GRP   32
#define HW    16384   // 128*128
#define KTOP  21      // int(32/3*2)

// ---------------- scratch (static device globals; no allocation) ----------------
__device__ uint32_t d_pooled_t[BATCH*CHN*PIX];   // tf32
__device__ uint32_t d_xpre3  [256*3072];         // [hi | lo | hi] per row
__device__ uint32_t d_WT_t   [PIX*PIX];          // gcn_weight^T tf32
__device__ uint32_t d_vw_t   [PIX*PIX];          // gcn_v_w tf32
__device__ uint32_t d_kw_t   [PQ*PIX];           // k_w tf32
__device__ uint32_t d_valw_t [PIX*PIX];          // v_w tf32
__device__ uint32_t d_qw_t   [PQ*PIX];           // q_w tf32
__device__ uint32_t d_qw3    [PQ*3072];          // gcn_q_w [hi | hi | lo]
__device__ uint32_t d_kw3    [PQ*3072];          // gcn_k_w [hi | hi | lo]
__device__ uint32_t d_av_t   [BATCH*GRP*PIX];    // tf32
__device__ float    d_gcnout [BATCH*GRP*PIX];
__device__ uint32_t d_gcnout_t[BATCH*GRP*PIX];   // tf32
__device__ float d_key   [BATCH*CHN*PQ];         // reduced key (phase-2 reduce)
__device__ float d_atten [BATCH*CHN*GRP];
__device__ float d_tuT   [BATCH*PIX*CHN];
__device__ float d_Gpart [BATCH*8*CHN*CHN];
__device__ float d_part  [8388608];              // split-K partials (32 MB)

// ---------------- helpers ----------------
__device__ __forceinline__ float wmax(float v) {
    #pragma unroll
    for (int o = 16; o > 0; o >>= 1) v = fmaxf(v, __shfl_xor_sync(0xffffffffu, v, o));
    return v;
}
__device__ __forceinline__ float wsum(float v) {
    #pragma unroll
    for (int o = 16; o > 0; o >>= 1) v += __shfl_xor_sync(0xffffffffu, v, o);
    return v;
}
__device__ __forceinline__ uint32_t f2tf32(float x) {
    uint32_t r;
    asm("cvt.rna.tf32.f32 %0, %1;" : "=r"(r) : "f"(x));
    return r;
}
__device__ __forceinline__ void mma_tf32(float* d, const uint32_t* a, const uint32_t* b) {
    asm volatile(
        "mma.sync.aligned.m16n8k8.row.col.f32.tf32.tf32.f32 "
        "{%0,%1,%2,%3}, {%4,%5,%6,%7}, {%8,%9}, {%0,%1,%2,%3};\n"
        : "+f"(d[0]), "+f"(d[1]), "+f"(d[2]), "+f"(d[3])
        : "r"(a[0]), "r"(a[1]), "r"(a[2]), "r"(a[3]), "r"(b[0]), "r"(b[1]));
}
__device__ __forceinline__ void cp16(uint32_t dst, const void* src) {
    asm volatile("cp.async.cg.shared.global [%0], [%1], 16;" :: "r"(dst), "l"(src));
}

// ---------------- 1. merged preprocessing: pool+xpre3 | transW | convw ----------------
__global__ void __launch_bounds__(256) prep_k(const float* __restrict__ x,
                                              const float* __restrict__ W,
                                              const float* __restrict__ vw,
                                              const float* __restrict__ kw,
                                              const float* __restrict__ valw,
                                              const float* __restrict__ qw,
                                              const float* __restrict__ gqw,
                                              const float* __restrict__ gkw)
{
    __shared__ float ts[32][33];
    const int blk = blockIdx.x;
    if (blk < 256) {
        const int bg = blk;
        const int b = bg >> 5, g = bg & 31;
        const int c0 = g << 1;
        const float* xp0 = x + ((size_t)(b * CHN + c0)) * HW;
        const float* xp1 = xp0 + HW;
        uint32_t* pl0 = d_pooled_t + (size_t)(b * CHN + c0) * PIX;
        uint32_t* xpr3 = d_xpre3 + (size_t)bg * 3072;
        for (int p = threadIdx.x; p < PIX; p += 256) {
            const int h4 = p >> 5, w4 = p & 31;
            const int off = (h4 * 4) * 128 + w4 * 4;
            float s0 = 0.f, s1 = 0.f;
            #pragma unroll
            for (int i = 0; i < 4; i++) {
                float4 r0 = *(const float4*)(xp0 + off + i * 128);
                float4 r1 = *(const float4*)(xp1 + off + i * 128);
                s0 += r0.x + r0.y + r0.z + r0.w;
                s1 += r1.x + r1.y + r1.z + r1.w;
            }
            pl0[p]       = f2tf32(s0 * (1.f / 16.f));
            pl0[PIX + p] = f2tf32(s1 * (1.f / 16.f));
            const float xv = (s0 + s1) * (1.f / 32.f);
            const uint32_t hi = f2tf32(xv);
            const uint32_t lo = f2tf32(xv - __uint_as_float(hi));
            xpr3[p]        = hi;
            xpr3[1024 + p] = lo;
            xpr3[2048 + p] = hi;
        }
    } else if (blk < 1280) {
        const int bi = blk - 256;
        const int bx = bi & 31, by = bi >> 5;
        const int tx = threadIdx.x & 31, ty = threadIdx.x >> 5;
        #pragma unroll
        for (int r = ty; r < 32; r += 8)
            ts[r][tx] = W[(size_t)(by * 32 + r) * PIX + bx * 32 + tx];
        __syncthreads();
        #pragma unroll
        for (int r = ty; r < 32; r += 8)
            d_WT_t[(size_t)(bx * 32 + r) * PIX + by * 32 + tx] = f2tf32(ts[tx][r]);
    } else {
        const int i = (blk - 1280) * 256 + threadIdx.x;
        if (i < 1048576) {
            d_vw_t[i] = f2tf32(vw[i]);
        } else if (i < 1310720) {
            d_kw_t[i - 1048576] = f2tf32(kw[i - 1048576]);
        } else if (i < 2359296) {
            d_valw_t[i - 1310720] = f2tf32(valw[i - 1310720]);
        } else if (i < 2621440) {
            d_qw_t[i - 2359296] = f2tf32(qw[i - 2359296]);
        } else if (i < 2883584) {
            const int j = i - 2621440;
            const int r = j >> 10, c = j & 1023;
            const float xv = gqw[j];
            const uint32_t hi = f2tf32(xv);
            const uint32_t lo = f2tf32(xv - __uint_as_float(hi));
            d_qw3[(size_t)r * 3072 + c]        = hi;
            d_qw3[(size_t)r * 3072 + 1024 + c] = hi;
            d_qw3[(size_t)r * 3072 + 2048 + c] = lo;
        } else if (i < 3145728) {
            const int j = i - 2883584;
            const int r = j >> 10, c = j & 1023;
            const float xv = gkw[j];
            const uint32_t hi = f2tf32(xv);
            const uint32_t lo = f2tf32(xv - __uint_as_float(hi));
            d_kw3[(size_t)r * 3072 + c]        = hi;
            d_kw3[(size_t)r * 3072 + 1024 + c] = hi;
            d_kw3[(size_t)r * 3072 + 2048 + c] = lo;
        }
    }
}

// ---------------- 2. problem structs ----------------
struct GProb {
    const uint32_t* A; const uint32_t* B; float* Cp;
    int M, N, tm, tn, tile_begin, kch, lda, ldb;
};
struct GBatch { GProb p[4]; int n; };

// ---------------- 3. tf32 tensor-core GEMM (128x128, cp.async double-buffer) ----------------
__global__ void __launch_bounds__(256, 2) gemmtc_k(GBatch gb)
{
    extern __shared__ uint32_t sm[];
    uint32_t* Abuf = sm;
    uint32_t* Bbuf = sm + 2 * 128 * 36;

    const int bid = blockIdx.x;
    GProb pr = gb.p[0];
    #pragma unroll
    for (int i = 1; i < 4; i++)
        if (i < gb.n && bid >= gb.p[i].tile_begin) pr = gb.p[i];

    const int local = bid - pr.tile_begin;
    const int tmn = pr.tm * pr.tn;
    const int ks = local / tmn;
    const int t = local - ks * tmn;
    const int m0 = (t / pr.tn) << 7;
    const int n0 = (t % pr.tn) << 7;

    const int tid = threadIdx.x;
    const int lane = tid & 31;
    const int w = tid >> 5;
    const int wm = (w & 1) << 6;
    const int wn = (w >> 1) << 5;

    const int lrow = tid >> 1;
    const int lseg = (tid & 1) << 4;

    const uint32_t* Aptr = pr.A + (size_t)(m0 + lrow) * pr.lda + ks * pr.kch + lseg;
    const uint32_t* Bptr = pr.B + (size_t)(n0 + lrow) * pr.ldb + ks * pr.kch + lseg;
    const int nchunk = pr.kch >> 5;

    const uint32_t sa = (uint32_t)__cvta_generic_to_shared(&Abuf[lrow * 36 + lseg]);
    const uint32_t sb = (uint32_t)__cvta_generic_to_shared(&Bbuf[lrow * 36 + lseg]);
    const uint32_t bufstride = 128 * 36 * 4;

    float acc[4][4][4];
    #pragma unroll
    for (int i = 0; i < 4; i++)
        #pragma unroll
        for (int j = 0; j < 4; j++)
            #pragma unroll
            for (int q = 0; q < 4; q++) acc[i][j][q] = 0.f;

    const int fr = lane >> 2;
    const int fc = lane & 3;

    {
        cp16(sa, Aptr); cp16(sa + 16, Aptr + 4); cp16(sa + 32, Aptr + 8); cp16(sa + 48, Aptr + 12);
        cp16(sb, Bptr); cp16(sb + 16, Bptr + 4); cp16(sb + 32, Bptr + 8); cp16(sb + 48, Bptr + 12);
        asm volatile("cp.async.commit_group;");
    }

    for (int c = 0; c < nchunk; c++) {
        if (c + 1 < nchunk) {
            const uint32_t dsta = sa + ((c + 1) & 1) * bufstride;
            const uint32_t dstb = sb + ((c + 1) & 1) * bufstride;
            const uint32_t* ga = Aptr + (c + 1) * 32;
            const uint32_t* gb2 = Bptr + (c + 1) * 32;
            cp16(dsta, ga); cp16(dsta + 16, ga + 4); cp16(dsta + 32, ga + 8); cp16(dsta + 48, ga + 12);
            cp16(dstb, gb2); cp16(dstb + 16, gb2 + 4); cp16(dstb + 32, gb2 + 8); cp16(dstb + 48, gb2 + 12);
            asm volatile("cp.async.commit_group;");
            asm volatile("cp.async.wait_group 1;");
        } else {
            asm volatile("cp.async.wait_group 0;");
        }
        __syncthreads();

        const uint32_t* As = Abuf + (c & 1) * 128 * 36;
        const uint32_t* Bs = Bbuf + (c & 1) * 128 * 36;
        #pragma unroll
        for (int kst = 0; kst < 4; kst++) {
            const int k0 = kst << 3;
            uint32_t afr[4][4];
            #pragma unroll
            for (int mi = 0; mi < 4; mi++) {
                const int r0 = wm + (mi << 4) + fr;
                afr[mi][0] = As[r0 * 36 + k0 + fc];
                afr[mi][1] = As[(r0 + 8) * 36 + k0 + fc];
                afr[mi][2] = As[r0 * 36 + k0 + fc + 4];
                afr[mi][3] = As[(r0 + 8) * 36 + k0 + fc + 4];
            }
            uint32_t bfr[4][2];
            #pragma unroll
            for (int ni = 0; ni < 4; ni++) {
                const int cn = wn + (ni << 3) + fr;
                bfr[ni][0] = Bs[cn * 36 + k0 + fc];
                bfr[ni][1] = Bs[cn * 36 + k0 + fc + 4];
            }
            #pragma unroll
            for (int mi = 0; mi < 4; mi++)
                #pragma unroll
                for (int ni = 0; ni < 4; ni++)
                    mma_tf32(acc[mi][ni], afr[mi], bfr[ni]);
        }
        __syncthreads();
    }

    float* dst = pr.Cp + (size_t)ks * pr.M * pr.N;
    #pragma unroll
    for (int mi = 0; mi < 4; mi++) {
        const int mA = m0 + wm + (mi << 4) + fr;
        #pragma unroll
        for (int ni = 0; ni < 4; ni++) {
            const int n = n0 + wn + (ni << 3) + (fc << 1);
            *(float2*)(dst + (size_t)mA * pr.N + n)       = make_float2(acc[mi][ni][0], acc[mi][ni][1]);
            *(float2*)(dst + (size_t)(mA + 8) * pr.N + n) = make_float2(acc[mi][ni][2], acc[mi][ni][3]);
        }
    }
}

// ---------------- 4. split-K reduce + bias (gcnout + key) ----------------
struct RProb {
    const float* Cp; float* C; const float* bias; uint32_t* Ct;
    int MN4, N4, elem_begin, ksl;
};
struct RBatch { RProb p[4]; int n; int total; };

__global__ void __launch_bounds__(256) reduce_batch_k(RBatch rb)
{
    const int e = blockIdx.x * 256 + threadIdx.x;
    if (e >= rb.total) return;
    RProb pr = rb.p[0];
    #pragma unroll
    for (int i = 1; i < 4; i++)
        if (i < rb.n && e >= rb.p[i].elem_begin) pr = rb.p[i];
    const int local = e - pr.elem_begin;
    const int n4 = local % pr.N4;
    const float4* src = (const float4*)pr.Cp + local;
    float4 s = make_float4(0.f, 0.f, 0.f, 0.f);
    #pragma unroll 4
    for (int ks = 0; ks < pr.ksl; ks++) {
        float4 p = src[(size_t)ks * pr.MN4];
        s.x += p.x; s.y += p.y; s.z += p.z; s.w += p.w;
    }
    float4 bb = ((const float4*)pr.bias)[n4];
    s.x += bb.x; s.y += bb.y; s.z += bb.z; s.w += bb.w;
    ((float4*)pr.C)[local] = s;
    if (pr.Ct) {
        uint4 tv;
        tv.x = f2tf32(s.x); tv.y = f2tf32(s.y); tv.z = f2tf32(s.z); tv.w = f2tf32(s.w);
        ((uint4*)pr.Ct)[local] = tv;
    }
}

// ---------------- 5. fused adjav, split over pixel quarters: grid (8 b, 4 pq)
// Each block: stage qg/kg (24-slice reduce, redundant x4 — L2-resident),
// compute full adj (cheap), then av for its 256-pixel quarter (v 8-slice reduce).
// phase-1: qg @0 [24][65536], kg @1572864 [24][65536], v @3145728 [8][262144]
__global__ void __launch_bounds__(1024) adjav_k(const float* __restrict__ qb,
                                                const float* __restrict__ kb,
                                                const float* __restrict__ vb)
{
    extern __shared__ float smf[];
    float* qgS  = smf;                   // [32][257]
    float* kgS  = smf + 32 * 257;        // [32][257]
    float* adjS = smf + 2 * 32 * 257;    // [32][33]
    const int b = blockIdx.x;
    const int pq0 = blockIdx.y << 8;     // pixel quarter base: 0/256/512/768
    const int tid = threadIdx.x;

    for (int i = tid; i < 32 * 256; i += 1024) {
        const int s = i >> 8, d = i & 255;
        const int gidx = (b * 32 + s) * 256 + d;
        float sq = qb[d], sk = kb[d];
        #pragma unroll 8
        for (int ks = 0; ks < 24; ks++) {
            sq += d_part[ks * 65536 + gidx];
            sk += d_part[1572864 + ks * 65536 + gidx];
        }
        qgS[s * 257 + d] = sq;
        kgS[s * 257 + d] = sk;
    }
    __syncthreads();

    const int s = tid >> 5, t = tid & 31;
    {
        float acc = 0.f;
        #pragma unroll 8
        for (int d = 0; d < 256; d++)
            acc += kgS[s * 257 + d] * qgS[t * 257 + d];
        float m = wmax(acc);
        float e = expf(acc - m);
        float v = e / wsum(e);
        int rank = 0;
        #pragma unroll
        for (int j = 0; j < 32; j++) {
            float vj = __shfl_sync(0xffffffffu, v, j);
            rank += (vj > v) || (vj == v && j < t);
        }
        const bool keep = rank < KTOP;
        float v2 = keep ? v : -INFINITY;
        float m2 = wmax(v2);
        float e2 = keep ? expf(v - m2) : 0.f;
        float s2 = wsum(e2);
        adjS[s * 33 + t] = e2 / s2;
    }
    __syncthreads();

    // av for this block's 256-pixel quarter; 1024 threads handle 256 pixels:
    // thread = (pg, pp): pg = tid>>8 (4 groups), pp = tid&255; each (pg) does 8 s-rows.
    const int pp = tid & 255;
    const int pg = tid >> 8;             // 0..3 -> s rows pg*8..pg*8+7
    const int p = pq0 + pp;
    float vreg[32];
    #pragma unroll
    for (int g = 0; g < 32; g++) {
        float sv = vb[p];
        const int gidx = (b * 32 + g) * 1024 + p;
        #pragma unroll
        for (int ks = 0; ks < 8; ks++)
            sv += d_part[3145728 + ks * 262144 + gidx];
        vreg[g] = sv;
    }
    #pragma unroll
    for (int si = pg * 8; si < pg * 8 + 8; si++) {
        float acc = 0.f;
        #pragma unroll
        for (int g = 0; g < 32; g++) acc += adjS[si * 33 + g] * vreg[g];
        d_av_t[(size_t)(b * 32 + si) * 1024 + p] = f2tf32(acc);
    }
}

// ---------------- 6. atten: q2 8-slice reduce @2097152, key pre-reduced ----------------
__global__ void __launch_bounds__(256) atten_k(const float* __restrict__ qb2)
{
    __shared__ float Qs[GRP][PQ + 4];
    const int b = blockIdx.x;
    const int cg = blockIdx.y;
    const int tid = threadIdx.x;
    for (int i = tid; i < GRP * PQ; i += 256) {
        const int g = i >> 8, d = i & 255;
        float s = qb2[d];
        const int gidx = (b * 32 + g) * 256 + d;
        #pragma unroll
        for (int ks = 0; ks < 8; ks++)
            s += d_part[2097152 + ks * 65536 + gidx];
        Qs[g][d] = s;
    }
    __syncthreads();
    const int w = tid >> 5, g = tid & 31;
    const int c = cg * 8 + w;
    const float* krow = d_key + (size_t)(b * CHN + c) * PQ;
    float acc = 0.f;
    #pragma unroll 4
    for (int d = 0; d < PQ; d++)
        acc += __ldg(krow + d) * Qs[g][d];
    float m = wmax(acc);
    float e = expf(acc - m);
    d_atten[(b * CHN + c) * GRP + g] = e / wsum(e);
}

// ---------------- 7. tu = atten @ value (value partials @0, 8 slices) ----------------
__global__ void __launch_bounds__(256) tu_k(const float* __restrict__ valb)
{
    __shared__ float attS[CHN][GRP + 1];
    __shared__ float vS[GRP][128];
    const int b = blockIdx.x;
    const int p0 = blockIdx.y << 7;
    const int tid = threadIdx.x;
    for (int i = tid; i < CHN * GRP; i += 256)
        attS[i >> 5][i & 31] = d_atten[b * CHN * GRP + i];
    for (int i = tid; i < GRP * 128; i += 256) {
        const int g = i >> 7, pp = i & 127;
        float s = valb[p0 + pp];
        const int gidx = (b * 32 + g) * 1024 + p0 + pp;
        #pragma unroll
        for (int ks = 0; ks < 8; ks++)
            s += d_part[ks * 262144 + gidx];
        vS[g][pp] = s;
    }
    __syncthreads();
    const int c = tid & 63;
    const int pr = tid >> 6;
    for (int pp = pr; pp < 128; pp += 4) {
        float acc = 0.f;
        #pragma unroll
        for (int g = 0; g < GRP; g++) acc += attS[c][g] * vS[g][pp];
        d_tuT[(size_t)b * 65536 + (size_t)(p0 + pp) * 64 + c] = acc;
    }
}

// ---------------- 8. Gram partials ----------------
__global__ void __launch_bounds__(256) gpart_k()
{
    __shared__ float Ts[128][65];
    const int b = blockIdx.x;
    const int k0 = blockIdx.y << 7;
    const int tid = threadIdx.x;
    for (int i = tid; i < 64 * 128; i += 256) {
        const int c = i >> 7, k = i & 127;
        Ts[k][c] = d_tuT[(size_t)b * 65536 + (size_t)c * 1024 + k0 + k];
    }
    __syncthreads();
    const int tx = tid & 15, ty = tid >> 4;
    float acc[4][4] = {};
    for (int k = 0; k < 128; k++) {
        float a0 = Ts[k][(ty << 2) + 0], a1 = Ts[k][(ty << 2) + 1];
        float a2 = Ts[k][(ty << 2) + 2], a3 = Ts[k][(ty << 2) + 3];
        float b0 = Ts[k][(tx << 2) + 0], b1 = Ts[k][(tx << 2) + 1];
        float b2 = Ts[k][(tx << 2) + 2], b3 = Ts[k][(tx << 2) + 3];
        acc[0][0] += a0 * b0; acc[0][1] += a0 * b1; acc[0][2] += a0 * b2; acc[0][3] += a0 * b3;
        acc[1][0] += a1 * b0; acc[1][1] += a1 * b1; acc[1][2] += a1 * b2; acc[1][3] += a1 * b3;
        acc[2][0] += a2 * b0; acc[2][1] += a2 * b1; acc[2][2] += a2 * b2; acc[2][3] += a2 * b3;
        acc[3][0] += a3 * b0; acc[3][1] += a3 * b1; acc[3][2] += a3 * b2; acc[3][3] += a3 * b3;
    }
    float* dst = d_Gpart + (size_t)(b * 8 + blockIdx.y) * 4096;
    #pragma unroll
    for (int i = 0; i < 4; i++)
        #pragma unroll
        for (int j = 0; j < 4; j++)
            dst[((ty << 2) + i) * 64 + (tx << 2) + j] = acc[i][j];
}

// ---------------- 9. out = G @ x_flat — tf32 tc, Gpart reduce fused into staging ----------------
__global__ void __launch_bounds__(256) finaltc_k(const float* __restrict__ x,
                                                 float* __restrict__ out)
{
    __shared__ uint32_t Gs[64][68];
    const int b = blockIdx.y;
    const int tid = threadIdx.x;
    const int lane = tid & 31, w = tid >> 5;
    const int fr = lane >> 2, fc = lane & 3;

    for (int i = tid; i < 4096; i += 256) {
        float s = 0.f;
        #pragma unroll
        for (int kc = 0; kc < 8; kc++)
            s += d_Gpart[(size_t)(b * 8 + kc) * 4096 + i];
        Gs[i >> 6][i & 63] = f2tf32(s);
    }
    __syncthreads();

    const int ng = (blockIdx.x << 8) + (w << 5);
    const float* xb = x + (size_t)b * CHN * HW;

    float acc[4][4][4];
    #pragma unroll
    for (int i = 0; i < 4; i++)
        #pragma unroll
        for (int j = 0; j < 4; j++)
            #pragma unroll
            for (int q = 0; q < 4; q++) acc[i][j][q] = 0.f;

    uint32_t bcur[4][2], bnxt[4][2];
    #pragma unroll
    for (int ni = 0; ni < 4; ni++) {
        const int n = ng + (ni << 3) + fr;
        bcur[ni][0] = f2tf32(__ldg(xb + (size_t)fc * HW + n));
        bcur[ni][1] = f2tf32(__ldg(xb + (size_t)(fc + 4) * HW + n));
        bnxt[ni][0] = 0; bnxt[ni][1] = 0;
    }

    #pragma unroll
    for (int kst = 0; kst < 8; kst++) {
        const int k0 = kst << 3;
        if (kst < 7) {
            #pragma unroll
            for (int ni = 0; ni < 4; ni++) {
                const int n = ng + (ni << 3) + fr;
                bnxt[ni][0] = f2tf32(__ldg(xb + (size_t)(k0 + 8 + fc) * HW + n));
                bnxt[ni][1] = f2tf32(__ldg(xb + (size_t)(k0 + 12 + fc) * HW + n));
            }
        }
        #pragma unroll
        for (int mi = 0; mi < 4; mi++) {
            uint32_t a[4];
            const int m0 = (mi << 4) + fr;
            a[0] = Gs[m0][k0 + fc];
            a[1] = Gs[m0 + 8][k0 + fc];
            a[2] = Gs[m0][k0 + fc + 4];
            a[3] = Gs[m0 + 8][k0 + fc + 4];
            #pragma unroll
            for (int ni = 0; ni < 4; ni++)
                mma_tf32(acc[mi][ni], a, bcur[ni]);
        }
        #pragma unroll
        for (int ni = 0; ni < 4; ni++) {
            bcur[ni][0] = bnxt[ni][0];
            bcur[ni][1] = bnxt[ni][1];
        }
    }

    float* ob = out + (size_t)b * CHN * HW;
    #pragma unroll
    for (int mi = 0; mi < 4; mi++) {
        const int m = (mi << 4) + fr;
        #pragma unroll
        for (int ni = 0; ni < 4; ni++) {
            const int n = ng + (ni << 3) + (fc << 1);
            *(float2*)(ob + (size_t)m * HW + n)       = make_float2(acc[mi][ni][0], acc[mi][ni][1]);
            *(float2*)(ob + (size_t)(m + 8) * HW + n) = make_float2(acc[mi][ni][2], acc[mi][ni][3]);
        }
    }
}

// ---------------- host launcher ----------------
extern "C" void kernel_launch(void* const* d_in, const int* in_sizes, int n_in,
                              void* d_out, int out_size)
{
    (void)in_sizes; (void)n_in; (void)out_size;
    const float* x          = (const float*)d_in[0];
    const float* gcn_weight = (const float*)d_in[1];
    const float* gcn_bias   = (const float*)d_in[2];
    const float* gcn_q_w    = (const float*)d_in[3];
    const float* gcn_q_b    = (const float*)d_in[4];
    const float* gcn_k_w    = (const float*)d_in[5];
    const float* gcn_k_b    = (const float*)d_in[6];
    const float* gcn_v_w    = (const float*)d_in[7];
    const float* gcn_v_b    = (const float*)d_in[8];
    const float* q_w        = (const float*)d_in[9];
    const float* q_b        = (const float*)d_in[10];
    const float* k_w        = (const float*)d_in[11];
    const float* k_b        = (const float*)d_in[12];
    const float* v_w        = (const float*)d_in[13];
    const float* v_b        = (const float*)d_in[14];
    float* out = (float*)d_out;

    float *p_part, *p_gcnout, *p_key;
    uint32_t *p_pooled_t, *p_xpre3, *p_WT_t, *p_vw_t, *p_kw_t, *p_valw_t, *p_qw_t,
             *p_qw3, *p_kw3, *p_av_t, *p_gcnout_t;
    cudaGetSymbolAddress((void**)&p_part,     d_part);
    cudaGetSymbolAddress((void**)&p_gcnout,   d_gcnout);
    cudaGetSymbolAddress((void**)&p_key,      d_key);
    cudaGetSymbolAddress((void**)&p_pooled_t, d_pooled_t);
    cudaGetSymbolAddress((void**)&p_xpre3,    d_xpre3);
    cudaGetSymbolAddress((void**)&p_WT_t,     d_WT_t);
    cudaGetSymbolAddress((void**)&p_vw_t,     d_vw_t);
    cudaGetSymbolAddress((void**)&p_kw_t,     d_kw_t);
    cudaGetSymbolAddress((void**)&p_valw_t,   d_valw_t);
    cudaGetSymbolAddress((void**)&p_qw_t,     d_qw_t);
    cudaGetSymbolAddress((void**)&p_qw3,      d_qw3);
    cudaGetSymbolAddress((void**)&p_kw3,      d_kw3);
    cudaGetSymbolAddress((void**)&p_av_t,     d_av_t);
    cudaGetSymbolAddress((void**)&p_gcnout_t, d_gcnout_t);

    cudaFuncSetAttribute(gemmtc_k, cudaFuncAttributeMaxDynamicSharedMemorySize, 73728);
    cudaFuncSetAttribute(adjav_k, cudaFuncAttributeMaxDynamicSharedMemorySize, 70016);
    const int TCSMEM = 73728;
    const int AJSMEM = (2 * 32 * 257 + 32 * 33) * 4;

    // merged preprocessing
    prep_k<<<13568, 256>>>(x, gcn_weight, gcn_v_w, k_w, v_w, q_w, gcn_q_w, gcn_k_w);

    // ---- Phase 1: {qg3(ks24), kg3(ks24), v(ks8), key(ks8)} — uniform 4-chunk blocks ----
    {
        GBatch gb{};
        gb.p[0] = { p_xpre3,    p_qw3,  p_part + 0,       256, 256,  2, 2, 0,   128, 3072, 3072 };
        gb.p[1] = { p_xpre3,    p_kw3,  p_part + 1572864, 256, 256,  2, 2, 96,  128, 3072, 3072 };
        gb.p[2] = { p_xpre3,    p_vw_t, p_part + 3145728, 256, 1024, 2, 8, 192, 128, 3072, 1024 };
        gb.p[3] = { p_pooled_t, p_kw_t, p_part + 5242880, 512, 256,  4, 2, 320, 128, 1024, 1024 };
        gb.n = 4;
        gemmtc_k<<<384, 256, TCSMEM>>>(gb);
    }

    adjav_k<<<dim3(BATCH, 4), 1024, AJSMEM>>>(gcn_q_b, gcn_k_b, gcn_v_b);

    // ---- Phase 2: gcnout = av @ WT, KS=8 -> 128 blocks; reduce gcnout + key ----
    {
        GBatch gb{};
        gb.p[0] = { p_av_t, p_WT_t, p_part, 256, 1024, 2, 8, 0, 128, 1024, 1024 };
        gb.n = 1;
        gemmtc_k<<<2 * 8 * 8, 256, TCSMEM>>>(gb);

        RBatch rb{};
        rb.p[0] = { p_part,           p_gcnout, gcn_bias, p_gcnout_t, 256 * 1024 / 4, 1024 / 4, 0,     8 };
        rb.p[1] = { p_part + 5242880, p_key,    k_b,      nullptr,    512 * 256 / 4,  256 / 4,  65536, 8 };
        rb.n = 2; rb.total = 65536 + 32768;
        reduce_batch_k<<<(rb.total + 255) / 256, 256>>>(rb);
    }

    // ---- Phase 3: {value(ks8), q2(ks8)} — 160 blocks ----
    {
        GBatch gb{};
        gb.p[0] = { p_gcnout_t, p_valw_t, p_part + 0,       256, 1024, 2, 8, 0,   128, 1024, 1024 };
        gb.p[1] = { p_gcnout_t, p_qw_t,   p_part + 2097152, 256, 256,  2, 2, 128, 128, 1024, 1024 };
        gb.n = 2;
        gemmtc_k<<<160, 256, TCSMEM>>>(gb);
    }

    atten_k<<<dim3(BATCH, 8), 256>>>(q_b);
    tu_k<<<dim3(BATCH, 8), 256>>>(v_b);
    gpart_k<<<dim3(BATCH, 8), 256>>>();
    finaltc_k<<<dim3(64, BATCH), 256>>>(x, out);
}